// round 1
// baseline (speedup 1.0000x reference)
#include <cuda_runtime.h>
#include <cstdint>

// Problem constants
#define BNv 256      // B*N = 4*64
#define Dv  2048
#define Cv  256
#define Ev  128
#define Mv  4096
#define Vv  10

// Scratch (static device globals -- allocation-free)
__device__ float g_xp[(size_t)Cv * BNv * Ev];   // [c][bn][e]  32 MB
__device__ float g_esq[(size_t)Cv * Mv];        // [c][m]      4 MB
__device__ int   g_idx[(size_t)BNv * Cv];       // [bn][c]

// ---------------------------------------------------------------------------
// Kernel 0: e_sq[c][m] = sum_e codebook[c][m][e]^2   (warp per row)
// ---------------------------------------------------------------------------
__global__ void __launch_bounds__(256) esq_kernel(const float* __restrict__ cb) {
    int row  = (blockIdx.x * 256 + threadIdx.x) >> 5;  // (c*Mv + m)
    int lane = threadIdx.x & 31;
    float4 v = *(const float4*)(cb + (size_t)row * Ev + lane * 4);
    float s = v.x * v.x + v.y * v.y + v.z * v.z + v.w * v.w;
    #pragma unroll
    for (int o = 16; o; o >>= 1) s += __shfl_xor_sync(0xffffffffu, s, o);
    if (lane == 0) g_esq[row] = s;
}

// ---------------------------------------------------------------------------
// Kernel 1: xp[c][bn][e] = emb[bn][:] . rp[c][:][e]
// Per block: one c, one 64-row bn tile. Tile: 64(bn) x 128(e), BK=16.
// Thread tile 4x8. 1024 blocks (c-major so 4 blocks sharing rp[c] cosched).
// ---------------------------------------------------------------------------
__global__ void __launch_bounds__(256) stage1_kernel(const float* __restrict__ emb,
                                                     const float* __restrict__ rp) {
    const int c   = blockIdx.x >> 2;
    const int bn0 = (blockIdx.x & 3) * 64;
    const float* __restrict__ Bp = rp + (size_t)c * (Dv * Ev);

    __shared__ float As[16][66];   // [k][bn], stride 66 -> conflict-free transpose store
    __shared__ float Bs[16][132];  // [k][e]

    const int tid = threadIdx.x;
    const int tx  = tid & 15;      // e groups
    const int ty  = tid >> 4;      // bn groups

    // load-index precompute
    const int am = tid >> 2;           // 0..63 bn row
    const int ak = (tid & 3) * 4;      // k quad
    const int bk = tid >> 4;           // 0..15 k row
    const int be = (tid & 15) * 8;     // e offset

    float acc[4][8];
    #pragma unroll
    for (int i = 0; i < 4; i++)
        #pragma unroll
        for (int j = 0; j < 8; j++) acc[i][j] = 0.f;

    for (int k0 = 0; k0 < Dv; k0 += 16) {
        float4 av  = *(const float4*)(emb + (size_t)(bn0 + am) * Dv + k0 + ak);
        float4 bv0 = *(const float4*)(Bp + (size_t)(k0 + bk) * Ev + be);
        float4 bv1 = *(const float4*)(Bp + (size_t)(k0 + bk) * Ev + be + 4);
        __syncthreads();   // previous tile fully consumed
        As[ak + 0][am] = av.x;
        As[ak + 1][am] = av.y;
        As[ak + 2][am] = av.z;
        As[ak + 3][am] = av.w;
        *(float4*)&Bs[bk][be]     = bv0;
        *(float4*)&Bs[bk][be + 4] = bv1;
        __syncthreads();

        #pragma unroll
        for (int kk = 0; kk < 16; kk++) {
            float a[4], b[8];
            #pragma unroll
            for (int i = 0; i < 4; i++) a[i] = As[kk][ty * 4 + i];
            #pragma unroll
            for (int j = 0; j < 8; j++) b[j] = Bs[kk][tx + 16 * j];
            #pragma unroll
            for (int i = 0; i < 4; i++)
                #pragma unroll
                for (int j = 0; j < 8; j++) acc[i][j] += a[i] * b[j];
        }
    }

    // store xp[c][bn][e], e = tx + 16*j
    #pragma unroll
    for (int i = 0; i < 4; i++) {
        size_t base = ((size_t)c * BNv + bn0 + ty * 4 + i) * Ev;
        #pragma unroll
        for (int j = 0; j < 8; j++)
            g_xp[base + tx + 16 * j] = acc[i][j];
    }
}

// ---------------------------------------------------------------------------
// Kernel 2: per (c, bn-tile) block: for all m in [0,4096):
//   score = e_sq[c][m] - 2 * (xp[c][bn] . cb[c][m]) ; argmin over m.
// XP tile (64x128) resident in smem; 32 codebook tiles of 128x128 streamed.
// Thread tile 4(bn) x 8(m), float4 dot along e. Dynamic smem ~99 KB.
// ---------------------------------------------------------------------------
__global__ void __launch_bounds__(256) stage2_kernel(const float* __restrict__ cb) {
    extern __shared__ float sm[];
    float (*Xs)[132] = (float(*)[132])sm;                 // 64 rows
    float (*Cs)[132] = (float(*)[132])(sm + 64 * 132);    // 128 rows

    const int c   = blockIdx.x >> 2;
    const int bn0 = (blockIdx.x & 3) * 64;
    const int tid = threadIdx.x;
    const int tx  = tid & 15;   // m groups
    const int ty  = tid >> 4;   // bn groups (0..15)

    const float* __restrict__ xp  = g_xp + ((size_t)c * BNv + bn0) * Ev;
    const float* __restrict__ cbp = cb + (size_t)c * Mv * Ev;
    const float* __restrict__ esq = g_esq + (size_t)c * Mv;

    // Load XP tile once (coalesced, conflict-free STS)
    {
        const int e4 = (tid & 31) * 4;
        const int r0 = tid >> 5;
        #pragma unroll
        for (int p = 0; p < 8; p++) {
            int r = r0 + p * 8;
            *(float4*)&Xs[r][e4] = *(const float4*)(xp + (size_t)r * Ev + e4);
        }
    }

    float best[4];
    int   bidx[4];
    #pragma unroll
    for (int i = 0; i < 4; i++) { best[i] = 3.4e38f; bidx[i] = 0; }

    const int le4 = (tid & 31) * 4;
    const int lr0 = tid >> 5;

    for (int m0 = 0; m0 < Mv; m0 += 128) {
        // load codebook tile 128 x 128
        #pragma unroll
        for (int p = 0; p < 16; p++) {
            int r = lr0 + p * 8;
            *(float4*)&Cs[r][le4] = *(const float4*)(cbp + (size_t)(m0 + r) * Ev + le4);
        }
        __syncthreads();

        float acc[4][8];
        #pragma unroll
        for (int i = 0; i < 4; i++)
            #pragma unroll
            for (int j = 0; j < 8; j++) acc[i][j] = 0.f;

        #pragma unroll 8
        for (int e = 0; e < Ev; e += 4) {
            float4 a[4], b[8];
            #pragma unroll
            for (int i = 0; i < 4; i++) a[i] = *(const float4*)&Xs[ty * 4 + i][e];
            #pragma unroll
            for (int j = 0; j < 8; j++) b[j] = *(const float4*)&Cs[tx + 16 * j][e];
            #pragma unroll
            for (int i = 0; i < 4; i++)
                #pragma unroll
                for (int j = 0; j < 8; j++) {
                    acc[i][j] += a[i].x * b[j].x;
                    acc[i][j] += a[i].y * b[j].y;
                    acc[i][j] += a[i].z * b[j].z;
                    acc[i][j] += a[i].w * b[j].w;
                }
        }

        // epilogue: score + running argmin (j ascending => m ascending per lane)
        #pragma unroll
        for (int j = 0; j < 8; j++) {
            int m = m0 + tx + 16 * j;
            float eq = esq[m];
            #pragma unroll
            for (int i = 0; i < 4; i++) {
                float s = eq - 2.f * acc[i][j];
                if (s < best[i]) { best[i] = s; bidx[i] = m; }
            }
        }
        __syncthreads();
    }

    // reduce across 16 m-lanes (halves of warp independent, xor<=8 stays in half)
    #pragma unroll
    for (int i = 0; i < 4; i++) {
        float v = best[i];
        int   id = bidx[i];
        #pragma unroll
        for (int o = 8; o >= 1; o >>= 1) {
            float v2 = __shfl_xor_sync(0xffffffffu, v, o);
            int   i2 = __shfl_xor_sync(0xffffffffu, id, o);
            if (v2 < v || (v2 == v && i2 < id)) { v = v2; id = i2; }
        }
        if (tx == 0) g_idx[(size_t)(bn0 + ty * 4 + i) * Cv + c] = id;
    }
}

// ---------------------------------------------------------------------------
// Kernel 3: out[bn][v] = mean_c values[c][idx[bn][c]][v]   (deterministic)
// ---------------------------------------------------------------------------
__global__ void __launch_bounds__(256) stage3_kernel(const float* __restrict__ vals,
                                                     float* __restrict__ out) {
    __shared__ float sh[256][Vv];
    const int bn = blockIdx.x;
    const int c  = threadIdx.x;
    int m = g_idx[(size_t)bn * Cv + c];
    const float* vp = vals + ((size_t)c * Mv + m) * Vv;
    #pragma unroll
    for (int v = 0; v < Vv; v++) sh[c][v] = vp[v];
    __syncthreads();
    if (c < Vv) {
        float s = 0.f;
        for (int k = 0; k < 256; k++) s += sh[k][c];
        out[(size_t)bn * Vv + c] = s * (1.f / 256.f);
    }
}

// ---------------------------------------------------------------------------
extern "C" void kernel_launch(void* const* d_in, const int* in_sizes, int n_in,
                              void* d_out, int out_size) {
    const float* emb  = (const float*)d_in[0];  // (B,N,D)
    const float* rp   = (const float*)d_in[1];  // (C,D,E)
    const float* cb   = (const float*)d_in[2];  // (C,M,E)
    const float* vals = (const float*)d_in[3];  // (C,M,V)
    float* out = (float*)d_out;                 // (B,N,V)

    const int smem2 = (64 + 128) * 132 * (int)sizeof(float);  // 101376 B
    cudaFuncSetAttribute(stage2_kernel, cudaFuncAttributeMaxDynamicSharedMemorySize, smem2);

    esq_kernel<<<(Cv * Mv) / 8, 256>>>(cb);
    stage1_kernel<<<Cv * 4, 256>>>(emb, rp);
    stage2_kernel<<<Cv * 4, 256, smem2>>>(cb);
    stage3_kernel<<<BNv, 256>>>(vals, out);
}

// round 3
// speedup vs baseline: 2.6364x; 2.6364x over previous
#include <cuda_runtime.h>
#include <cuda_bf16.h>
#include <cstdint>

// Problem constants
#define BNv 256
#define Dv  2048
#define Cv  256
#define Ev  128
#define Mv  4096
#define Vv  10

#define KEXT 144                 // 128 cb + esq_hi + esq_lo + 14 zeros
#define ROWB (KEXT * 2)          // 288 bytes per bf16 row
#define SSTR 304                 // padded smem row stride (288+16), conflict-free ldmatrix

// Scratch
__device__ float g_xp[(size_t)Cv * BNv * Ev];
__device__ float g_esq[(size_t)Cv * Mv];
__device__ int   g_idx[(size_t)BNv * Cv];
__device__ int   g_cand[(size_t)BNv * Cv * 8];
__device__ __align__(16) unsigned char g_cbb[(size_t)Cv * Mv * ROWB]; // bf16 ext rows

// ---------------------------------------------------------------------------
__device__ __forceinline__ uint32_t smem_u32(const void* p) {
    uint32_t a;
    asm("{ .reg .u64 t; cvta.to.shared.u64 t, %1; cvt.u32.u64 %0, t; }" : "=r"(a) : "l"(p));
    return a;
}
__device__ __forceinline__ void cp16(uint32_t dst, const void* src) {
    asm volatile("cp.async.cg.shared.global [%0], [%1], 16;" :: "r"(dst), "l"(src) : "memory");
}
__device__ __forceinline__ void cp_commit() { asm volatile("cp.async.commit_group;" ::: "memory"); }
__device__ __forceinline__ void cp_wait0()  { asm volatile("cp.async.wait_group 0;"  ::: "memory"); }

__device__ __forceinline__ void ldm4(uint32_t& r0, uint32_t& r1, uint32_t& r2, uint32_t& r3, uint32_t a) {
    asm volatile("ldmatrix.sync.aligned.m8n8.x4.shared.b16 {%0,%1,%2,%3}, [%4];"
                 : "=r"(r0), "=r"(r1), "=r"(r2), "=r"(r3) : "r"(a));
}
__device__ __forceinline__ void mma16816(float* c, const uint32_t* a, uint32_t b0, uint32_t b1) {
    asm volatile("mma.sync.aligned.m16n8k16.row.col.f32.bf16.bf16.f32 "
                 "{%0,%1,%2,%3}, {%4,%5,%6,%7}, {%8,%9}, {%0,%1,%2,%3};"
                 : "+f"(c[0]), "+f"(c[1]), "+f"(c[2]), "+f"(c[3])
                 : "r"(a[0]), "r"(a[1]), "r"(a[2]), "r"(a[3]), "r"(b0), "r"(b1));
}
__device__ __forceinline__ uint32_t pack_bf2(float x, float y) {
    return ((uint32_t)__bfloat16_as_ushort(__float2bfloat16(y)) << 16) |
           __bfloat16_as_ushort(__float2bfloat16(x));
}

// ---------------------------------------------------------------------------
// prep: codebook -> bf16 ext rows [cb | esq_hi | esq_lo | zeros], + g_esq
// warp per (c,m) row
// ---------------------------------------------------------------------------
__global__ void __launch_bounds__(256) prep_kernel(const float* __restrict__ cb) {
    int row  = (blockIdx.x * 256 + threadIdx.x) >> 5;
    int lane = threadIdx.x & 31;
    float4 v = *(const float4*)(cb + (size_t)row * Ev + lane * 4);
    float s = v.x * v.x + v.y * v.y + v.z * v.z + v.w * v.w;
    #pragma unroll
    for (int o = 16; o; o >>= 1) s += __shfl_xor_sync(0xffffffffu, s, o);

    unsigned char* dst = g_cbb + (size_t)row * ROWB;
    uint2 u;
    u.x = pack_bf2(v.x, v.y);
    u.y = pack_bf2(v.z, v.w);
    *(uint2*)(dst + lane * 8) = u;

    if (lane == 0) {
        g_esq[row] = s;
        __nv_bfloat16 hi = __float2bfloat16(s);
        float lo = s - __bfloat162float(hi);
        *(uint32_t*)(dst + 256) =
            ((uint32_t)__bfloat16_as_ushort(__float2bfloat16(lo)) << 16) |
            __bfloat16_as_ushort(hi);
    } else if (lane < 8) {
        *(uint32_t*)(dst + 256 + lane * 4) = 0u;
    }
}

// ---------------------------------------------------------------------------
// stage1: xp = emb . rp  (fp32 SIMT, unchanged; passed R1)
// ---------------------------------------------------------------------------
__global__ void __launch_bounds__(256) stage1_kernel(const float* __restrict__ emb,
                                                     const float* __restrict__ rp) {
    const int c   = blockIdx.x >> 2;
    const int bn0 = (blockIdx.x & 3) * 64;
    const float* __restrict__ Bp = rp + (size_t)c * (Dv * Ev);

    __shared__ float As[16][66];
    __shared__ float Bs[16][132];

    const int tid = threadIdx.x;
    const int tx  = tid & 15;
    const int ty  = tid >> 4;
    const int am = tid >> 2;
    const int ak = (tid & 3) * 4;
    const int bk = tid >> 4;
    const int be = (tid & 15) * 8;

    float acc[4][8];
    #pragma unroll
    for (int i = 0; i < 4; i++)
        #pragma unroll
        for (int j = 0; j < 8; j++) acc[i][j] = 0.f;

    for (int k0 = 0; k0 < Dv; k0 += 16) {
        float4 av  = *(const float4*)(emb + (size_t)(bn0 + am) * Dv + k0 + ak);
        float4 bv0 = *(const float4*)(Bp + (size_t)(k0 + bk) * Ev + be);
        float4 bv1 = *(const float4*)(Bp + (size_t)(k0 + bk) * Ev + be + 4);
        __syncthreads();
        As[ak + 0][am] = av.x;
        As[ak + 1][am] = av.y;
        As[ak + 2][am] = av.z;
        As[ak + 3][am] = av.w;
        *(float4*)&Bs[bk][be]     = bv0;
        *(float4*)&Bs[bk][be + 4] = bv1;
        __syncthreads();

        #pragma unroll
        for (int kk = 0; kk < 16; kk++) {
            float a[4], b[8];
            #pragma unroll
            for (int i = 0; i < 4; i++) a[i] = As[kk][ty * 4 + i];
            #pragma unroll
            for (int j = 0; j < 8; j++) b[j] = Bs[kk][tx + 16 * j];
            #pragma unroll
            for (int i = 0; i < 4; i++)
                #pragma unroll
                for (int j = 0; j < 8; j++) acc[i][j] += a[i] * b[j];
        }
    }
    #pragma unroll
    for (int i = 0; i < 4; i++) {
        size_t base = ((size_t)c * BNv + bn0 + ty * 4 + i) * Ev;
        #pragma unroll
        for (int j = 0; j < 8; j++)
            g_xp[base + tx + 16 * j] = acc[i][j];
    }
}

// ---------------------------------------------------------------------------
// mma stage: grid 512 = (c, mh). block 256 thr = 8 warps.
// X (256bn x 144k) resident bf16 smem; CB tiles 64m x 144k double-buffered.
// warp w: bn rows [32w, 32w+32), all 64 m of each tile.
// score = esq - 2*xp.cb lands directly in mma accumulators.
// ---------------------------------------------------------------------------
#define XS_BYTES (256 * SSTR)          // 77824
#define CB_BYTES (64 * SSTR)           // 19456
#define SMEM2 (XS_BYTES + 2 * CB_BYTES) // 116736

__global__ void __launch_bounds__(256, 1) mma_kernel() {
    extern __shared__ __align__(16) unsigned char sm[];
    const uint32_t smb = smem_u32(sm);
    const int tid  = threadIdx.x;
    const int w    = tid >> 5;
    const int lane = tid & 31;
    const int c  = blockIdx.x >> 1;
    const int mh = blockIdx.x & 1;

    // ---- build X rows: [-2*xp | 1 | 1 | zeros], one row per thread
    {
        const int r = tid;
        const float* xr = g_xp + ((size_t)c * BNv + r) * Ev;
        unsigned char* xd = sm + (size_t)r * SSTR;
        #pragma unroll 8
        for (int q = 0; q < 32; q++) {
            float4 v = *(const float4*)(xr + q * 4);
            uint2 u;
            u.x = pack_bf2(-2.f * v.x, -2.f * v.y);
            u.y = pack_bf2(-2.f * v.z, -2.f * v.w);
            *(uint2*)(xd + q * 8) = u;
        }
        *(uint32_t*)(xd + 256) = 0x3F803F80u;   // 1.0, 1.0 (bf16)
        #pragma unroll
        for (int t = 0; t < 7; t++) *(uint32_t*)(xd + 260 + t * 4) = 0u;
    }

    // ---- first CB tile prefetch
    const size_t cb_base = (size_t)(c * Mv + mh * 2048) * ROWB;
    const uint32_t cbs = smb + XS_BYTES;
    {
        #pragma unroll
        for (int s = 0; s < 5; s++) {
            int idx = tid + s * 256;
            if (idx < 1152) {
                int row = idx / 18, ch = idx % 18;
                cp16(cbs + row * SSTR + ch * 16, g_cbb + cb_base + (size_t)row * ROWB + ch * 16);
            }
        }
        cp_commit();
    }

    // lane constants
    const int grp = lane >> 3;
    const uint32_t a_off = ((grp & 1) * 8 + (lane & 7)) * SSTR + (grp >> 1) * 16;
    const uint32_t b_off = ((grp >> 1) * 8 + (lane & 7)) * SSTR + (grp & 1) * 16;
    const uint32_t xw = smb + (w * 32) * SSTR + a_off;

    // top-3 per row-slot (4 slots)
    float ts[4][3];
    int   tm[4][3];
    #pragma unroll
    for (int r = 0; r < 4; r++)
        #pragma unroll
        for (int e = 0; e < 3; e++) { ts[r][e] = 3.4e38f; tm[r][e] = 0; }

    for (int it = 0; it < 32; it++) {
        const int buf = it & 1;
        cp_wait0();
        __syncthreads();                 // tile(it) ready; compute(it-1) done everywhere
        if (it < 31) {                   // prefetch next tile into other buffer
            const uint32_t dst = cbs + (buf ^ 1) * CB_BYTES;
            const size_t src = cb_base + (size_t)(it + 1) * 64 * ROWB;
            #pragma unroll
            for (int s = 0; s < 5; s++) {
                int idx = tid + s * 256;
                if (idx < 1152) {
                    int row = idx / 18, ch = idx % 18;
                    cp16(dst + row * SSTR + ch * 16, g_cbb + src + (size_t)row * ROWB + ch * 16);
                }
            }
            cp_commit();
        }

        float acc[2][8][4];
        #pragma unroll
        for (int i = 0; i < 2; i++)
            #pragma unroll
            for (int j = 0; j < 8; j++)
                #pragma unroll
                for (int e = 0; e < 4; e++) acc[i][j][e] = 0.f;

        const uint32_t cw = cbs + buf * CB_BYTES + b_off;

        #pragma unroll
        for (int ks = 0; ks < 9; ks++) {
            uint32_t A[2][4], B[8][2];
            #pragma unroll
            for (int i = 0; i < 2; i++)
                ldm4(A[i][0], A[i][1], A[i][2], A[i][3], xw + i * 16 * SSTR + ks * 32);
            #pragma unroll
            for (int jj = 0; jj < 4; jj++) {
                uint32_t r0, r1, r2, r3;
                ldm4(r0, r1, r2, r3, cw + jj * 16 * SSTR + ks * 32);
                B[2 * jj][0] = r0; B[2 * jj][1] = r1;
                B[2 * jj + 1][0] = r2; B[2 * jj + 1][1] = r3;
            }
            #pragma unroll
            for (int i = 0; i < 2; i++)
                #pragma unroll
                for (int j = 0; j < 8; j++)
                    mma16816(acc[i][j], A[i], B[j][0], B[j][1]);
        }

        // epilogue: top-3 updates (scores already include esq)
        const int mb = it * 64 + (lane & 3) * 2;
        #pragma unroll
        for (int i = 0; i < 2; i++)
            #pragma unroll
            for (int j = 0; j < 8; j++) {
                const int m0 = mb + j * 8;
                #pragma unroll
                for (int half = 0; half < 2; half++) {       // c0,c1 = row; c2,c3 = row+8
                    const int rs = i * 2 + half;
                    #pragma unroll
                    for (int e = 0; e < 2; e++) {
                        float v = acc[i][j][half * 2 + e];
                        int   m = m0 + e;
                        if (v < ts[rs][2]) {
                            if (v < ts[rs][1]) {
                                if (v < ts[rs][0]) {
                                    ts[rs][2]=ts[rs][1]; tm[rs][2]=tm[rs][1];
                                    ts[rs][1]=ts[rs][0]; tm[rs][1]=tm[rs][0];
                                    ts[rs][0]=v; tm[rs][0]=m;
                                } else {
                                    ts[rs][2]=ts[rs][1]; tm[rs][2]=tm[rs][1];
                                    ts[rs][1]=v; tm[rs][1]=m;
                                }
                            } else { ts[rs][2]=v; tm[rs][2]=m; }
                        }
                    }
                }
            }
        __syncthreads();   // done reading tile(it) before next overwrite
    }

    // ---- quad merge (lanes q=0..3 own the same rows) -> top-4 -> g_cand
    const uint32_t FULL = 0xffffffffu;
    #pragma unroll
    for (int rs = 0; rs < 4; rs++) {
        float m4s[4] = {3.4e38f, 3.4e38f, 3.4e38f, 3.4e38f};
        int   m4i[4] = {0, 0, 0, 0};
        #pragma unroll
        for (int src = 0; src < 4; src++) {
            #pragma unroll
            for (int e = 0; e < 3; e++) {
                float vs = __shfl_sync(FULL, ts[rs][e], (lane & ~3) + src);
                int   vm = __shfl_sync(FULL, tm[rs][e], (lane & ~3) + src);
                if ((lane & 3) == 0) {
                    if (vs < m4s[3]) {
                        if (vs < m4s[1]) {
                            if (vs < m4s[0]) {
                                m4s[3]=m4s[2]; m4i[3]=m4i[2]; m4s[2]=m4s[1]; m4i[2]=m4i[1];
                                m4s[1]=m4s[0]; m4i[1]=m4i[0]; m4s[0]=vs; m4i[0]=vm;
                            } else {
                                m4s[3]=m4s[2]; m4i[3]=m4i[2]; m4s[2]=m4s[1]; m4i[2]=m4i[1];
                                m4s[1]=vs; m4i[1]=vm;
                            }
                        } else {
                            if (vs < m4s[2]) { m4s[3]=m4s[2]; m4i[3]=m4i[2]; m4s[2]=vs; m4i[2]=vm; }
                            else             { m4s[3]=vs; m4i[3]=vm; }
                        }
                    }
                }
            }
        }
        if ((lane & 3) == 0) {
            int bn = w * 32 + (rs >> 1) * 16 + (lane >> 2) + (rs & 1) * 8;
            size_t base = ((size_t)bn * Cv + c) * 8 + mh * 4;
            #pragma unroll
            for (int t = 0; t < 4; t++) g_cand[base + t] = mh * 2048 + m4i[t];
        }
    }
}

// ---------------------------------------------------------------------------
// rescore: exact fp32 over 8 candidates per (bn,c); warp per pair
// ---------------------------------------------------------------------------
__global__ void __launch_bounds__(256) rescore_kernel(const float* __restrict__ cb) {
    int wp   = (blockIdx.x * 256 + threadIdx.x) >> 5;
    int lane = threadIdx.x & 31;
    int bn   = wp >> 8;
    int c    = wp & 255;
    float4 x = *(const float4*)(g_xp + ((size_t)c * BNv + bn) * Ev + lane * 4);
    float best = 3.4e38f; int bm = Mv;
    #pragma unroll
    for (int t = 0; t < 8; t++) {
        int m = g_cand[((size_t)bn * Cv + c) * 8 + t];
        float4 cv = *(const float4*)(cb + ((size_t)c * Mv + m) * Ev + lane * 4);
        float d = x.x * cv.x + x.y * cv.y + x.z * cv.z + x.w * cv.w;
        #pragma unroll
        for (int o = 16; o; o >>= 1) d += __shfl_xor_sync(0xffffffffu, d, o);
        float s = g_esq[(size_t)c * Mv + m] - 2.f * d;
        if (s < best || (s == best && m < bm)) { best = s; bm = m; }
    }
    if (lane == 0) g_idx[(size_t)bn * Cv + c] = bm;
}

// ---------------------------------------------------------------------------
__global__ void __launch_bounds__(256) stage3_kernel(const float* __restrict__ vals,
                                                     float* __restrict__ out) {
    __shared__ float sh[256][Vv];
    const int bn = blockIdx.x;
    const int c  = threadIdx.x;
    int m = g_idx[(size_t)bn * Cv + c];
    const float* vp = vals + ((size_t)c * Mv + m) * Vv;
    #pragma unroll
    for (int v = 0; v < Vv; v++) sh[c][v] = vp[v];
    __syncthreads();
    if (c < Vv) {
        float s = 0.f;
        for (int k = 0; k < 256; k++) s += sh[k][c];
        out[(size_t)bn * Vv + c] = s * (1.f / 256.f);
    }
}

// ---------------------------------------------------------------------------
extern "C" void kernel_launch(void* const* d_in, const int* in_sizes, int n_in,
                              void* d_out, int out_size) {
    const float* emb  = (const float*)d_in[0];
    const float* rp   = (const float*)d_in[1];
    const float* cb   = (const float*)d_in[2];
    const float* vals = (const float*)d_in[3];
    float* out = (float*)d_out;

    cudaFuncSetAttribute(mma_kernel, cudaFuncAttributeMaxDynamicSharedMemorySize, SMEM2);

    prep_kernel<<<(Cv * Mv) / 8, 256>>>(cb);
    stage1_kernel<<<Cv * 4, 256>>>(emb, rp);
    mma_kernel<<<Cv * 2, 256, SMEM2>>>();
    rescore_kernel<<<(BNv * Cv) / 8, 256>>>(cb);
    stage3_kernel<<<BNv, 256>>>(vals, out);
}

// round 9
// speedup vs baseline: 3.1119x; 1.1804x over previous
#include <cuda_runtime.h>
#include <cuda_bf16.h>
#include <cstdint>

// Problem constants
#define BNv 256
#define Dv  2048
#define Cv  256
#define Ev  128
#define Mv  4096
#define Vv  10

#define KEXT 144
#define ROWB (KEXT * 2)
#define SSTR 304

// Scratch
__device__ float g_xp[(size_t)Cv * BNv * Ev];
__device__ float g_esq[(size_t)Cv * Mv];
__device__ int   g_idx[(size_t)BNv * Cv];
__device__ int   g_cand[(size_t)BNv * Cv * 8];
__device__ __align__(16) unsigned char g_cbb[(size_t)Cv * Mv * ROWB];

// ---------------------------------------------------------------------------
__device__ __forceinline__ uint32_t smem_u32(const void* p) {
    uint32_t a;
    asm("{ .reg .u64 t; cvta.to.shared.u64 t, %1; cvt.u32.u64 %0, t; }" : "=r"(a) : "l"(p));
    return a;
}
__device__ __forceinline__ void cp16(uint32_t dst, const void* src) {
    asm volatile("cp.async.cg.shared.global [%0], [%1], 16;" :: "r"(dst), "l"(src) : "memory");
}
__device__ __forceinline__ void cp_commit() { asm volatile("cp.async.commit_group;" ::: "memory"); }
__device__ __forceinline__ void cp_wait0()  { asm volatile("cp.async.wait_group 0;"  ::: "memory"); }

__device__ __forceinline__ void ldm4(uint32_t& r0, uint32_t& r1, uint32_t& r2, uint32_t& r3, uint32_t a) {
    asm volatile("ldmatrix.sync.aligned.m8n8.x4.shared.b16 {%0,%1,%2,%3}, [%4];"
                 : "=r"(r0), "=r"(r1), "=r"(r2), "=r"(r3) : "r"(a));
}
__device__ __forceinline__ void mma16816(float* c, const uint32_t* a, uint32_t b0, uint32_t b1) {
    asm volatile("mma.sync.aligned.m16n8k16.row.col.f32.bf16.bf16.f32 "
                 "{%0,%1,%2,%3}, {%4,%5,%6,%7}, {%8,%9}, {%0,%1,%2,%3};"
                 : "+f"(c[0]), "+f"(c[1]), "+f"(c[2]), "+f"(c[3])
                 : "r"(a[0]), "r"(a[1]), "r"(a[2]), "r"(a[3]), "r"(b0), "r"(b1));
}
__device__ __forceinline__ uint32_t pack_bf2(float x, float y) {
    return ((uint32_t)__bfloat16_as_ushort(__float2bfloat16(y)) << 16) |
           __bfloat16_as_ushort(__float2bfloat16(x));
}
// packed fp32x2 helpers (Blackwell FFMA2) -- each lane is an exact fp32 RN fma
__device__ __forceinline__ unsigned long long pack_ff(float x, float y) {
    unsigned long long r;
    asm("mov.b64 %0, {%1, %2};" : "=l"(r) : "f"(x), "f"(y));
    return r;
}
__device__ __forceinline__ void unpack_ff(unsigned long long d, float& x, float& y) {
    asm("mov.b64 {%0, %1}, %2;" : "=f"(x), "=f"(y) : "l"(d));
}
__device__ __forceinline__ void ffma2(unsigned long long& d, unsigned long long a, unsigned long long b) {
    asm("fma.rn.f32x2 %0, %1, %2, %0;" : "+l"(d) : "l"(a), "l"(b));
}

// ---------------------------------------------------------------------------
// prep: codebook -> bf16 ext rows [cb | esq_hi | esq_lo | zeros], + g_esq
// ---------------------------------------------------------------------------
__global__ void __launch_bounds__(256) prep_kernel(const float* __restrict__ cb) {
    int row  = (blockIdx.x * 256 + threadIdx.x) >> 5;
    int lane = threadIdx.x & 31;
    float4 v = *(const float4*)(cb + (size_t)row * Ev + lane * 4);
    float s = v.x * v.x + v.y * v.y + v.z * v.z + v.w * v.w;
    #pragma unroll
    for (int o = 16; o; o >>= 1) s += __shfl_xor_sync(0xffffffffu, s, o);

    unsigned char* dst = g_cbb + (size_t)row * ROWB;
    uint2 u;
    u.x = pack_bf2(v.x, v.y);
    u.y = pack_bf2(v.z, v.w);
    *(uint2*)(dst + lane * 8) = u;

    if (lane == 0) {
        g_esq[row] = s;
        __nv_bfloat16 hi = __float2bfloat16(s);
        float lo = s - __bfloat162float(hi);
        *(uint32_t*)(dst + 256) =
            ((uint32_t)__bfloat16_as_ushort(__float2bfloat16(lo)) << 16) |
            __bfloat16_as_ushort(hi);
    } else if (lane < 8) {
        *(uint32_t*)(dst + 256 + lane * 4) = 0u;
    }
}

// ---------------------------------------------------------------------------
// stage1: xp = emb . rp, fp32 with packed FFMA2 (f32x2).
// Numerics: per output element, acc = fma(a_k, b_k, acc) for k = 0..2047 in
// order -- bitwise identical to the scalar SIMT kernel that passed (R1/R3).
// grid 512 = (c = bx>>1, bn-half = bx&1). 256 thr / 8 warps.
// block tile 128bn x 128e; warp 32bn x 64e; thread 8bn x 8e = 4 bn-pairs x 8e.
// ---------------------------------------------------------------------------
__global__ void __launch_bounds__(256, 2) stage1_kernel(const float* __restrict__ emb,
                                                        const float* __restrict__ rp) {
    __shared__ __align__(16) float As[16][130];   // [k][bn]
    __shared__ __align__(16) float Bs[16][132];   // [k][e]

    const int t = threadIdx.x;
    const int c = blockIdx.x >> 1;
    const int bn0g = (blockIdx.x & 1) * 128;
    const float* __restrict__ bb = rp + (size_t)c * (Dv * Ev);

    const int wid  = t >> 5, lane = t & 31;
    const int wbn  = wid & 3;          // bn-warp (0..3) * 32
    const int we   = wid >> 2;         // e-warp  (0..1) * 64
    const int g    = lane >> 3;        // bn subgroup *8
    const int el   = lane & 7;         // e lane

    // LDG mappings
    const int arow = t >> 1;           // 0..127
    const int akq  = (t & 1) * 8;      // k offset 0 or 8
    const int bk   = t >> 4;           // 0..15
    const int be   = (t & 15) * 8;     // e offset

    const float* __restrict__ aptr = emb + (size_t)(bn0g + arow) * Dv + akq;
    const float* __restrict__ bptr = bb + (size_t)bk * Ev + be;

    float4 av0 = *(const float4*)(aptr);
    float4 av1 = *(const float4*)(aptr + 4);
    float4 bv0 = *(const float4*)(bptr);
    float4 bv1 = *(const float4*)(bptr + 4);

    unsigned long long acc2[4][8];
    #pragma unroll
    for (int p = 0; p < 4; p++)
        #pragma unroll
        for (int j = 0; j < 8; j++) acc2[p][j] = 0ull;

    const int abase = wbn * 32 + g * 8;
    const int ebase = we * 64 + el;

    for (int k0 = 0; k0 < Dv; k0 += 16) {
        __syncthreads();   // previous tile fully consumed
        As[akq + 0][arow] = av0.x;
        As[akq + 1][arow] = av0.y;
        As[akq + 2][arow] = av0.z;
        As[akq + 3][arow] = av0.w;
        As[akq + 4][arow] = av1.x;
        As[akq + 5][arow] = av1.y;
        As[akq + 6][arow] = av1.z;
        As[akq + 7][arow] = av1.w;
        *(float4*)&Bs[bk][be]     = bv0;
        *(float4*)&Bs[bk][be + 4] = bv1;
        __syncthreads();

        if (k0 + 16 < Dv) {
            av0 = *(const float4*)(aptr + (k0 + 16));
            av1 = *(const float4*)(aptr + (k0 + 16) + 4);
            bv0 = *(const float4*)(bptr + (size_t)(k0 + 16) * Ev);
            bv1 = *(const float4*)(bptr + (size_t)(k0 + 16) * Ev + 4);
        }

        #pragma unroll
        for (int kk = 0; kk < 16; kk++) {
            unsigned long long a2[4], b2[8];
            #pragma unroll
            for (int p = 0; p < 4; p++) {
                float2 af = *(const float2*)&As[kk][abase + 2 * p];
                a2[p] = pack_ff(af.x, af.y);
            }
            #pragma unroll
            for (int j = 0; j < 8; j++) {
                float bf = Bs[kk][ebase + 8 * j];
                b2[j] = pack_ff(bf, bf);
            }
            #pragma unroll
            for (int p = 0; p < 4; p++)
                #pragma unroll
                for (int j = 0; j < 8; j++)
                    ffma2(acc2[p][j], a2[p], b2[j]);
        }
    }

    // store xp: pair (bn, bn+1) same e
    #pragma unroll
    for (int p = 0; p < 4; p++) {
        const int bn = bn0g + abase + 2 * p;
        #pragma unroll
        for (int j = 0; j < 8; j++) {
            float v0, v1;
            unpack_ff(acc2[p][j], v0, v1);
            const size_t base = ((size_t)c * BNv + bn) * Ev + ebase + 8 * j;
            g_xp[base]      = v0;
            g_xp[base + Ev] = v1;
        }
    }
}

// ---------------------------------------------------------------------------
// mma stage (stage2): bf16 candidates, unchanged (passed R3)
// ---------------------------------------------------------------------------
#define XS_BYTES (256 * SSTR)
#define CB_BYTES (64 * SSTR)
#define SMEM2 (XS_BYTES + 2 * CB_BYTES)

__global__ void __launch_bounds__(256, 1) mma_kernel() {
    extern __shared__ __align__(16) unsigned char sm[];
    const uint32_t smb = smem_u32(sm);
    const int tid  = threadIdx.x;
    const int w    = tid >> 5;
    const int lane = tid & 31;
    const int c  = blockIdx.x >> 1;
    const int mh = blockIdx.x & 1;

    {
        const int r = tid;
        const float* xr = g_xp + ((size_t)c * BNv + r) * Ev;
        unsigned char* xd = sm + (size_t)r * SSTR;
        #pragma unroll 8
        for (int q = 0; q < 32; q++) {
            float4 v = *(const float4*)(xr + q * 4);
            uint2 u;
            u.x = pack_bf2(-2.f * v.x, -2.f * v.y);
            u.y = pack_bf2(-2.f * v.z, -2.f * v.w);
            *(uint2*)(xd + q * 8) = u;
        }
        *(uint32_t*)(xd + 256) = 0x3F803F80u;
        #pragma unroll
        for (int t = 0; t < 7; t++) *(uint32_t*)(xd + 260 + t * 4) = 0u;
    }

    const size_t cb_base = (size_t)(c * Mv + mh * 2048) * ROWB;
    const uint32_t cbs = smb + XS_BYTES;
    {
        #pragma unroll
        for (int s = 0; s < 5; s++) {
            int idx = tid + s * 256;
            if (idx < 1152) {
                int row = idx / 18, ch = idx % 18;
                cp16(cbs + row * SSTR + ch * 16, g_cbb + cb_base + (size_t)row * ROWB + ch * 16);
            }
        }
        cp_commit();
    }

    const int grp = lane >> 3;
    const uint32_t a_off = ((grp & 1) * 8 + (lane & 7)) * SSTR + (grp >> 1) * 16;
    const uint32_t b_off = ((grp >> 1) * 8 + (lane & 7)) * SSTR + (grp & 1) * 16;
    const uint32_t xw = smb + (w * 32) * SSTR + a_off;

    float ts[4][3];
    int   tm[4][3];
    #pragma unroll
    for (int r = 0; r < 4; r++)
        #pragma unroll
        for (int e = 0; e < 3; e++) { ts[r][e] = 3.4e38f; tm[r][e] = 0; }

    for (int it = 0; it < 32; it++) {
        const int buf = it & 1;
        cp_wait0();
        __syncthreads();
        if (it < 31) {
            const uint32_t dst = cbs + (buf ^ 1) * CB_BYTES;
            const size_t src = cb_base + (size_t)(it + 1) * 64 * ROWB;
            #pragma unroll
            for (int s = 0; s < 5; s++) {
                int idx = tid + s * 256;
                if (idx < 1152) {
                    int row = idx / 18, ch = idx % 18;
                    cp16(dst + row * SSTR + ch * 16, g_cbb + src + (size_t)row * ROWB + ch * 16);
                }
            }
            cp_commit();
        }

        float acc[2][8][4];
        #pragma unroll
        for (int i = 0; i < 2; i++)
            #pragma unroll
            for (int j = 0; j < 8; j++)
                #pragma unroll
                for (int e = 0; e < 4; e++) acc[i][j][e] = 0.f;

        const uint32_t cw = cbs + buf * CB_BYTES + b_off;

        #pragma unroll
        for (int ks = 0; ks < 9; ks++) {
            uint32_t A[2][4], B[8][2];
            #pragma unroll
            for (int i = 0; i < 2; i++)
                ldm4(A[i][0], A[i][1], A[i][2], A[i][3], xw + i * 16 * SSTR + ks * 32);
            #pragma unroll
            for (int jj = 0; jj < 4; jj++) {
                uint32_t r0, r1, r2, r3;
                ldm4(r0, r1, r2, r3, cw + jj * 16 * SSTR + ks * 32);
                B[2 * jj][0] = r0; B[2 * jj][1] = r1;
                B[2 * jj + 1][0] = r2; B[2 * jj + 1][1] = r3;
            }
            #pragma unroll
            for (int i = 0; i < 2; i++)
                #pragma unroll
                for (int j = 0; j < 8; j++)
                    mma16816(acc[i][j], A[i], B[j][0], B[j][1]);
        }

        const int mb = it * 64 + (lane & 3) * 2;
        #pragma unroll
        for (int i = 0; i < 2; i++)
            #pragma unroll
            for (int j = 0; j < 8; j++) {
                const int m0 = mb + j * 8;
                #pragma unroll
                for (int half = 0; half < 2; half++) {
                    const int rs = i * 2 + half;
                    #pragma unroll
                    for (int e = 0; e < 2; e++) {
                        float v = acc[i][j][half * 2 + e];
                        int   m = m0 + e;
                        if (v < ts[rs][2]) {
                            if (v < ts[rs][1]) {
                                if (v < ts[rs][0]) {
                                    ts[rs][2]=ts[rs][1]; tm[rs][2]=tm[rs][1];
                                    ts[rs][1]=ts[rs][0]; tm[rs][1]=tm[rs][0];
                                    ts[rs][0]=v; tm[rs][0]=m;
                                } else {
                                    ts[rs][2]=ts[rs][1]; tm[rs][2]=tm[rs][1];
                                    ts[rs][1]=v; tm[rs][1]=m;
                                }
                            } else { ts[rs][2]=v; tm[rs][2]=m; }
                        }
                    }
                }
            }
        __syncthreads();
    }

    const uint32_t FULL = 0xffffffffu;
    #pragma unroll
    for (int rs = 0; rs < 4; rs++) {
        float m4s[4] = {3.4e38f, 3.4e38f, 3.4e38f, 3.4e38f};
        int   m4i[4] = {0, 0, 0, 0};
        #pragma unroll
        for (int src = 0; src < 4; src++) {
            #pragma unroll
            for (int e = 0; e < 3; e++) {
                float vs = __shfl_sync(FULL, ts[rs][e], (lane & ~3) + src);
                int   vm = __shfl_sync(FULL, tm[rs][e], (lane & ~3) + src);
                if ((lane & 3) == 0) {
                    if (vs < m4s[3]) {
                        if (vs < m4s[1]) {
                            if (vs < m4s[0]) {
                                m4s[3]=m4s[2]; m4i[3]=m4i[2]; m4s[2]=m4s[1]; m4i[2]=m4i[1];
                                m4s[1]=m4s[0]; m4i[1]=m4i[0]; m4s[0]=vs; m4i[0]=vm;
                            } else {
                                m4s[3]=m4s[2]; m4i[3]=m4i[2]; m4s[2]=m4s[1]; m4i[2]=m4i[1];
                                m4s[1]=vs; m4i[1]=vm;
                            }
                        } else {
                            if (vs < m4s[2]) { m4s[3]=m4s[2]; m4i[3]=m4i[2]; m4s[2]=vs; m4i[2]=vm; }
                            else             { m4s[3]=vs; m4i[3]=vm; }
                        }
                    }
                }
            }
        }
        if ((lane & 3) == 0) {
            int bn = w * 32 + (rs >> 1) * 16 + (lane >> 2) + (rs & 1) * 8;
            size_t base = ((size_t)bn * Cv + c) * 8 + mh * 4;
            #pragma unroll
            for (int t = 0; t < 4; t++) g_cand[base + t] = mh * 2048 + m4i[t];
        }
    }
}

// ---------------------------------------------------------------------------
__global__ void __launch_bounds__(256) rescore_kernel(const float* __restrict__ cb) {
    int wp   = (blockIdx.x * 256 + threadIdx.x) >> 5;
    int lane = threadIdx.x & 31;
    int bn   = wp >> 8;
    int c    = wp & 255;
    float4 x = *(const float4*)(g_xp + ((size_t)c * BNv + bn) * Ev + lane * 4);
    float best = 3.4e38f; int bm = Mv;
    #pragma unroll
    for (int t = 0; t < 8; t++) {
        int m = g_cand[((size_t)bn * Cv + c) * 8 + t];
        float4 cv = *(const float4*)(cb + ((size_t)c * Mv + m) * Ev + lane * 4);
        float d = x.x * cv.x + x.y * cv.y + x.z * cv.z + x.w * cv.w;
        #pragma unroll
        for (int o = 16; o; o >>= 1) d += __shfl_xor_sync(0xffffffffu, d, o);
        float s = g_esq[(size_t)c * Mv + m] - 2.f * d;
        if (s < best || (s == best && m < bm)) { best = s; bm = m; }
    }
    if (lane == 0) g_idx[(size_t)bn * Cv + c] = bm;
}

// ---------------------------------------------------------------------------
__global__ void __launch_bounds__(256) stage3_kernel(const float* __restrict__ vals,
                                                     float* __restrict__ out) {
    __shared__ float sh[256][Vv];
    const int bn = blockIdx.x;
    const int c  = threadIdx.x;
    int m = g_idx[(size_t)bn * Cv + c];
    const float* vp = vals + ((size_t)c * Mv + m) * Vv;
    #pragma unroll
    for (int v = 0; v < Vv; v++) sh[c][v] = vp[v];
    __syncthreads();
    if (c < Vv) {
        float s = 0.f;
        for (int k = 0; k < 256; k++) s += sh[k][c];
        out[(size_t)bn * Vv + c] = s * (1.f / 256.f);
    }
}

// ---------------------------------------------------------------------------
extern "C" void kernel_launch(void* const* d_in, const int* in_sizes, int n_in,
                              void* d_out, int out_size) {
    const float* emb  = (const float*)d_in[0];
    const float* rp   = (const float*)d_in[1];
    const float* cb   = (const float*)d_in[2];
    const float* vals = (const float*)d_in[3];
    float* out = (float*)d_out;

    cudaFuncSetAttribute(mma_kernel, cudaFuncAttributeMaxDynamicSharedMemorySize, SMEM2);

    prep_kernel<<<(Cv * Mv) / 8, 256>>>(cb);
    stage1_kernel<<<Cv * 2, 256>>>(emb, rp);
    mma_kernel<<<Cv * 2, 256, SMEM2>>>();
    rescore_kernel<<<(BNv * Cv) / 8, 256>>>(cb);
    stage3_kernel<<<BNv, 256>>>(vals, out);
}